// round 17
// baseline (speedup 1.0000x reference)
#include <cuda_runtime.h>
#include <cuda_fp16.h>
#include <cstdint>

// ---------------- problem constants ----------------
#define Bv 8
#define Qv 1024
#define Sv 2048
#define Dm 1024
#define Hv 16
#define DH 64
#define MT 128            // q rows per CTA
#define ST 64             // s per tile
#define NTILES (Sv / ST)  // 32
#define NTH 256

// Q tile pitch (fp16 bytes) -- proven conflict-free for A ldmatrix
#define PB  72
#define PBB (PB * 2)      // 144 B per row

// ---------------- KA smem layout (bytes) ----------------
#define SM_QHI   0
#define SM_BIAS  (SM_QHI + MT * PBB)      // 18432 (2048 f32 = 8192 B)
#define SM_KV    (SM_BIAS + 8192)         // 26624: 3 bufs x 16384 (K 8K | V 8K)
#define SMEM_KA  (SM_KV + 3 * 16384)      // 75776 -> 2 CTAs/SM

// ---------------- KB smem layout (bytes) ----------------
#define SB_QHI   0
#define SB_BIAS  (SB_QHI + MT * PBB)      // 18432
#define SB_K     (SB_BIAS + 8192)         // 26624: 3 bufs x 8192 (K only)
#define SMEM_KB  (SB_K + 3 * 8192)        // 51200 -> 3 CTAs/SM (reg-capped 84)

// scratch: [b][h][tile][K|V][64 rows][128 B], XOR-swizzled 16B chunks  (64 MB)
__device__ __align__(16) unsigned char g_kv[(size_t)Bv * Hv * NTILES * 2 * ST * 128];
__device__ float g_rinv[Bv * Qv * Hv];

// ---------------- helpers ----------------
__device__ __forceinline__ uint32_t su32(const void* p) {
    uint32_t a;
    asm("{ .reg .u64 t; cvta.to.shared.u64 t, %1; cvt.u32.u64 %0, t; }" : "=r"(a) : "l"(p));
    return a;
}

__device__ __forceinline__ void cp_async16(uint32_t dst, const void* src) {
    asm volatile("cp.async.cg.shared.global [%0], [%1], 16;" :: "r"(dst), "l"(src));
}
#define CP_COMMIT() asm volatile("cp.async.commit_group;" ::: "memory")
#define CP_WAIT1()  asm volatile("cp.async.wait_group 1;" ::: "memory")

__device__ __forceinline__ void ldm4(uint32_t* r, uint32_t a) {
    asm volatile("ldmatrix.sync.aligned.m8n8.x4.shared.b16 {%0,%1,%2,%3}, [%4];"
        : "=r"(r[0]), "=r"(r[1]), "=r"(r[2]), "=r"(r[3]) : "r"(a));
}
__device__ __forceinline__ void ldm4t(uint32_t* r, uint32_t a) {
    asm volatile("ldmatrix.sync.aligned.m8n8.x4.trans.shared.b16 {%0,%1,%2,%3}, [%4];"
        : "=r"(r[0]), "=r"(r[1]), "=r"(r[2]), "=r"(r[3]) : "r"(a));
}
__device__ __forceinline__ void mma16816(float* d, const uint32_t* a, uint32_t b0, uint32_t b1) {
    asm volatile("mma.sync.aligned.m16n8k16.row.col.f32.f16.f16.f32 "
        "{%0,%1,%2,%3}, {%4,%5,%6,%7}, {%8,%9}, {%0,%1,%2,%3};"
        : "+f"(d[0]), "+f"(d[1]), "+f"(d[2]), "+f"(d[3])
        : "r"(a[0]), "r"(a[1]), "r"(a[2]), "r"(a[3]), "r"(b0), "r"(b1));
}

// streaming 8B store (write-once data: bypass L2 persistence)
__device__ __forceinline__ void stg_cs_f2(float* p, float x, float y) {
    asm volatile("st.global.cs.v2.f32 [%0], {%1, %2};" :: "l"(p), "f"(x), "f"(y) : "memory");
}

#define QSCALE (0.125f * 1.44269504088896f)
#define NEGBIG (-1e30f)

// ======================= K0: pre-convert K/V to fp16 swizzled tile images =======================
__global__ void __launch_bounds__(256)
split_k0(const float* __restrict__ Kg, const float* __restrict__ Vg)
{
    int gid = blockIdx.x * 256 + threadIdx.x;
    int c  = gid & 7;
    int s  = (gid >> 3) & 2047;
    int h  = (gid >> 14) & 15;
    int bb = (gid >> 18) & 7;
    int kv = gid >> 21;

    const float* src = (kv ? Vg : Kg) + ((size_t)bb * Sv + s) * Dm + h * DH + c * 8;
    float4 f0 = *(const float4*)src;
    float4 f1 = *(const float4*)(src + 4);
    __half2 h0 = __floats2half2_rn(f0.x, f0.y);
    __half2 h1 = __floats2half2_rn(f0.z, f0.w);
    __half2 h2 = __floats2half2_rn(f1.x, f1.y);
    __half2 h3 = __floats2half2_rn(f1.z, f1.w);

    int tile = s >> 6, row = s & 63;
    int cph  = c ^ (row & 7);                       // XOR swizzle
    size_t base = (((size_t)(bb * Hv + h) * NTILES + tile) * 2 + kv) * 8192
                + row * 128 + cph * 16;
    *(uint4*)(g_kv + base) = make_uint4(*(uint32_t*)&h0, *(uint32_t*)&h1,
                                        *(uint32_t*)&h2, *(uint32_t*)&h3);
}

// ======================= KA: pass A — rowsums + O + rinv =======================
extern __shared__ char smem[];

__global__ void __launch_bounds__(NTH, 2)
attn_ka(const float* __restrict__ Qg, const int* __restrict__ Mg,
        float* __restrict__ outg)
{
    const int tid  = threadIdx.x;
    const int lane = tid & 31;
    const int wq   = tid >> 5;
    const int q0   = blockIdx.x * MT;
    const int h    = blockIdx.y;
    const int b    = blockIdx.z;

    const uint32_t sb = su32(smem);
    float* bias = (float*)(smem + SM_BIAS);

    const unsigned char* kvbase = g_kv + (size_t)(b * Hv + h) * NTILES * 16384;

    // prime tiles 0 and 1 (two groups in flight)
    #pragma unroll
    for (int it = 0; it < 4; it++) {
        int idx = tid + it * NTH;
        cp_async16(sb + SM_KV + idx * 16, kvbase + idx * 16);
    }
    CP_COMMIT();
    #pragma unroll
    for (int it = 0; it < 4; it++) {
        int idx = tid + it * NTH;
        cp_async16(sb + SM_KV + 16384 + idx * 16, kvbase + 16384 + idx * 16);
    }
    CP_COMMIT();

    // prologue: Q (scaled, single fp16) + mask bias
    #pragma unroll 4
    for (int it = 0; it < 16; it++) {
        int idx = tid + it * NTH;
        int m = idx >> 5, dp = idx & 31;
        float2 v = *(const float2*)(Qg + ((size_t)(b * Qv + q0 + m)) * Dm + h * DH + dp * 2);
        __half2 qh = __floats2half2_rn(v.x * QSCALE, v.y * QSCALE);
        *(uint32_t*)(smem + SM_QHI + m * PBB + dp * 4) = *(uint32_t*)&qh;
    }
    for (int s = tid; s < Sv; s += NTH)
        bias[s] = Mg[(size_t)b * Sv + s] ? 0.0f : NEGBIG;

    // per-thread addresses
    const uint32_t aAoff = (uint32_t)((wq * 16 + (lane & 15)) * PBB + ((lane & 16) >> 4) * 16);
    const uint32_t aAhi = sb + SM_QHI + aAoff;
    const int s7 = lane & 7;
    const int cb = (lane & 8) >> 3;
    const int vb = (lane >> 4) & 1;
    const uint32_t rowK = (uint32_t)((lane & 7) + ((lane & 16) >> 1)) * 128;
    const uint32_t rowV = (uint32_t)((lane & 7) + (lane & 8)) * 128;
    uint32_t kc[4], vc[4];
    #pragma unroll
    for (int k4 = 0; k4 < 4; k4++) kc[k4] = (uint32_t)((((k4 << 1) | cb) ^ s7) << 4);
    #pragma unroll
    for (int np = 0; np < 4; np++) vc[np] = (uint32_t)((((np << 1) | vb) ^ s7) << 4);

    const int r = lane >> 2, c = lane & 3;

    float O[8][4];
    #pragma unroll
    for (int nt = 0; nt < 8; nt++)
        #pragma unroll
        for (int j = 0; j < 4; j++) O[nt][j] = 0.0f;
    float rsl = 0.0f, rsh = 0.0f;

    for (int i = 0; i < NTILES; i++) {
        CP_WAIT1();        // tile i group complete (<=1 pending: tile i+1)
        __syncthreads();   // tile i visible to all; buf (i+2)%3 free (tile i-1 done)

        if (i + 2 < NTILES) {
            const unsigned char* g = kvbase + (size_t)(i + 2) * 16384;
            uint32_t dst = sb + SM_KV + ((i + 2) % 3) * 16384;
            #pragma unroll
            for (int it = 0; it < 4; it++) {
                int idx = tid + it * NTH;
                cp_async16(dst + idx * 16, g + idx * 16);
            }
        }
        CP_COMMIT();

        const uint32_t bufK = sb + SM_KV + (i % 3) * 16384;

        // MMA1 single-pass: S = Q·K
        float S[8][4];
        #pragma unroll
        for (int nt = 0; nt < 8; nt++)
            #pragma unroll
            for (int j = 0; j < 4; j++) S[nt][j] = 0.0f;

        #pragma unroll
        for (int k4 = 0; k4 < 4; k4++) {
            uint32_t ah[4];
            ldm4(ah, aAhi + k4 * 32);
            #pragma unroll
            for (int np = 0; np < 4; np++) {
                uint32_t bo = rowK + np * 2048 + kc[k4];
                uint32_t bk[4];
                ldm4(bk, bufK + bo);
                mma16816(S[2*np],   ah, bk[0], bk[1]);
                mma16816(S[2*np+1], ah, bk[2], bk[3]);
            }
        }

        // exp2(S + bias) + rowsum
        const int s0 = i * ST;
        #pragma unroll
        for (int nt = 0; nt < 8; nt++) {
            int col = nt * 8 + 2 * c;
            float b0 = bias[s0 + col], b1 = bias[s0 + col + 1];
            float e0 = exp2f(S[nt][0] + b0);
            float e1 = exp2f(S[nt][1] + b1);
            float e2 = exp2f(S[nt][2] + b0);
            float e3 = exp2f(S[nt][3] + b1);
            rsl += e0 + e1; rsh += e2 + e3;
            S[nt][0] = e0; S[nt][1] = e1; S[nt][2] = e2; S[nt][3] = e3;
        }

        // MMA2: O += P·V
        const uint32_t bufV = bufK + 8192;
        #pragma unroll
        for (int kt = 0; kt < 4; kt++) {
            uint32_t ph[4];
            __half2 p0 = __floats2half2_rn(S[2*kt][0],   S[2*kt][1]);
            __half2 p1 = __floats2half2_rn(S[2*kt][2],   S[2*kt][3]);
            __half2 p2 = __floats2half2_rn(S[2*kt+1][0], S[2*kt+1][1]);
            __half2 p3 = __floats2half2_rn(S[2*kt+1][2], S[2*kt+1][3]);
            ph[0] = *(uint32_t*)&p0; ph[1] = *(uint32_t*)&p1;
            ph[2] = *(uint32_t*)&p2; ph[3] = *(uint32_t*)&p3;
            #pragma unroll
            for (int np = 0; np < 4; np++) {
                uint32_t bo = rowV + kt * 2048 + vc[np];
                uint32_t v4[4];
                ldm4t(v4, bufV + bo);
                mma16816(O[2*np],   ph, v4[0], v4[1]);
                mma16816(O[2*np+1], ph, v4[2], v4[3]);
            }
        }
    }

    // rowsum reduce, rinv, normalize O, write out + rinv
    rsl += __shfl_xor_sync(0xffffffffu, rsl, 1);
    rsl += __shfl_xor_sync(0xffffffffu, rsl, 2);
    rsh += __shfl_xor_sync(0xffffffffu, rsh, 1);
    rsh += __shfl_xor_sync(0xffffffffu, rsh, 2);
    const float il = 1.0f / (rsl + 1e-13f);
    const float ih = 1.0f / (rsh + 1e-13f);

    if (c == 0) {
        g_rinv[(size_t)(b * Qv + q0 + wq * 16 + r)     * Hv + h] = il;
        g_rinv[(size_t)(b * Qv + q0 + wq * 16 + r + 8) * Hv + h] = ih;
    }

    float* orow0 = outg + (size_t)(b * Qv + q0 + wq * 16 + r)     * Dm + h * DH;
    float* orow1 = outg + (size_t)(b * Qv + q0 + wq * 16 + r + 8) * Dm + h * DH;
    #pragma unroll
    for (int nt = 0; nt < 8; nt++) {
        int col = nt * 8 + 2 * c;
        stg_cs_f2(orow0 + col, O[nt][0] * il, O[nt][1] * il);
        stg_cs_f2(orow1 + col, O[nt][2] * ih, O[nt][3] * ih);
    }
}

// ======================= KB: pass B — recompute scores, write normalized attn =======================
__global__ void __launch_bounds__(NTH, 3)
attn_kb(const float* __restrict__ Qg, const int* __restrict__ Mg,
        float* __restrict__ attng)
{
    const int tid  = threadIdx.x;
    const int lane = tid & 31;
    const int wq   = tid >> 5;
    const int q0   = blockIdx.x * MT;
    const int h    = blockIdx.y;
    const int b    = blockIdx.z;

    const uint32_t sb = su32(smem);
    float* bias = (float*)(smem + SB_BIAS);

    const unsigned char* kvbase = g_kv + (size_t)(b * Hv + h) * NTILES * 16384;

    // prime tiles 0 and 1 (K images only)
    #pragma unroll
    for (int it = 0; it < 2; it++) {
        int idx = tid + it * NTH;
        cp_async16(sb + SB_K + idx * 16, kvbase + idx * 16);
    }
    CP_COMMIT();
    #pragma unroll
    for (int it = 0; it < 2; it++) {
        int idx = tid + it * NTH;
        cp_async16(sb + SB_K + 8192 + idx * 16, kvbase + 16384 + idx * 16);
    }
    CP_COMMIT();

    // prologue: Q (scaled fp16) + mask bias
    #pragma unroll 4
    for (int it = 0; it < 16; it++) {
        int idx = tid + it * NTH;
        int m = idx >> 5, dp = idx & 31;
        float2 v = *(const float2*)(Qg + ((size_t)(b * Qv + q0 + m)) * Dm + h * DH + dp * 2);
        __half2 qh = __floats2half2_rn(v.x * QSCALE, v.y * QSCALE);
        *(uint32_t*)(smem + SB_QHI + m * PBB + dp * 4) = *(uint32_t*)&qh;
    }
    for (int s = tid; s < Sv; s += NTH)
        bias[s] = Mg[(size_t)b * Sv + s] ? 0.0f : NEGBIG;

    // per-thread addresses
    const uint32_t aAoff = (uint32_t)((wq * 16 + (lane & 15)) * PBB + ((lane & 16) >> 4) * 16);
    const uint32_t aAhi = sb + SB_QHI + aAoff;
    const int s7 = lane & 7;
    const int cb = (lane & 8) >> 3;
    const uint32_t rowK = (uint32_t)((lane & 7) + ((lane & 16) >> 1)) * 128;
    uint32_t kc[4];
    #pragma unroll
    for (int k4 = 0; k4 < 4; k4++) kc[k4] = (uint32_t)((((k4 << 1) | cb) ^ s7) << 4);

    const int r = lane >> 2, c = lane & 3;

    // rinv folded into exp2 exponent
    const float il = g_rinv[(size_t)(b * Qv + q0 + wq * 16 + r)     * Hv + h];
    const float ih = g_rinv[(size_t)(b * Qv + q0 + wq * 16 + r + 8) * Hv + h];
    const float lgl = __log2f(il);
    const float lgh = __log2f(ih);

    float* arow0 = attng + (((size_t)(b * Qv + q0 + wq * 16 + r)) * Hv + h) * Sv;
    float* arow1 = attng + (((size_t)(b * Qv + q0 + wq * 16 + r + 8)) * Hv + h) * Sv;

    for (int i = 0; i < NTILES; i++) {
        CP_WAIT1();
        __syncthreads();

        if (i + 2 < NTILES) {
            const unsigned char* g = kvbase + (size_t)(i + 2) * 16384;
            uint32_t dst = sb + SB_K + ((i + 2) % 3) * 8192;
            #pragma unroll
            for (int it = 0; it < 2; it++) {
                int idx = tid + it * NTH;
                cp_async16(dst + idx * 16, g + idx * 16);
            }
        }
        CP_COMMIT();

        const uint32_t bufK = sb + SB_K + (i % 3) * 8192;

        // MMA1 single-pass: S = Q·K (identical rounding to KA)
        float S[8][4];
        #pragma unroll
        for (int nt = 0; nt < 8; nt++)
            #pragma unroll
            for (int j = 0; j < 4; j++) S[nt][j] = 0.0f;

        #pragma unroll
        for (int k4 = 0; k4 < 4; k4++) {
            uint32_t ah[4];
            ldm4(ah, aAhi + k4 * 32);
            #pragma unroll
            for (int np = 0; np < 4; np++) {
                uint32_t bo = rowK + np * 2048 + kc[k4];
                uint32_t bk[4];
                ldm4(bk, bufK + bo);
                mma16816(S[2*np],   ah, bk[0], bk[1]);
                mma16816(S[2*np+1], ah, bk[2], bk[3]);
            }
        }

        // attn = exp2(S + bias + lg(rinv)), streaming coalesced write
        const int s0 = i * ST;
        #pragma unroll
        for (int nt = 0; nt < 8; nt++) {
            int col = nt * 8 + 2 * c;
            float b0 = bias[s0 + col], b1 = bias[s0 + col + 1];
            stg_cs_f2(arow0 + s0 + col,
                      exp2f(S[nt][0] + b0 + lgl), exp2f(S[nt][1] + b1 + lgl));
            stg_cs_f2(arow1 + s0 + col,
                      exp2f(S[nt][2] + b0 + lgh), exp2f(S[nt][3] + b1 + lgh));
        }
    }
}

// ======================= launch =======================
extern "C" void kernel_launch(void* const* d_in, const int* in_sizes, int n_in,
                              void* d_out, int out_size)
{
    const float* Qg = (const float*)d_in[0];
    const float* Kg = (const float*)d_in[1];
    const float* Vg = (const float*)d_in[2];
    const int*   Mg = (const int*)d_in[3];

    float* outg  = (float*)d_out;                     // [B,Q,D]
    float* attng = outg + (size_t)Bv * Qv * Dm;       // [B,Q,H,S]

    // K0: pre-convert K/V (2^22 threads)
    split_k0<<<(2u << 21) / 256, 256>>>(Kg, Vg);

    dim3 grid(Qv / MT, Hv, Bv);                       // (8,16,8) = 1024 CTAs

    // KA: pass A (out + rinv)
    cudaFuncSetAttribute(attn_ka, cudaFuncAttributeMaxDynamicSharedMemorySize, SMEM_KA);
    attn_ka<<<grid, NTH, SMEM_KA>>>(Qg, Mg, outg);

    // KB: pass B (normalized attn), 3 CTAs/SM
    cudaFuncSetAttribute(attn_kb, cudaFuncAttributeMaxDynamicSharedMemorySize, SMEM_KB);
    attn_kb<<<grid, NTH, SMEM_KB>>>(Qg, Mg, attng);
}